// round 1
// baseline (speedup 1.0000x reference)
#include <cuda_runtime.h>

// CapLayer: fused capsule routing, never materializes pred [512,1152,10,16].
// x:    d_in[0]  float [512][256][6][6]   (channel = g*8+k, g<32, k<8)
// targ: d_in[1]  int   (unused)
// W:    d_in[2]  float [5120][8] ; flat idx = g*1280 + j*128 + d*8 + k
// bias: d_in[3]  float [5120]    ; flat idx = g*160  + j*16  + d
// out:  float [512][10][16]

#define LOG2E 1.4426950408889634f

struct Smem {
    float x[32 * 8 * 36];     // 9216  [g][k][hw]
    float c[32 * 10 * 36];    // 11520 [g][j][hw]
    float vW[10 * 32 * 8];    // 2560  [j][g][k]  (accumulated, pre-scaled by log2e)
    float vb[10 * 32];        // 320   [j][g]
    float cx[10 * 32 * 8];    // 2560  [j][g][k]
    float csum[10 * 32];      // 320   [j][g]
    float s[10 * 16];         // 160
    float v[10 * 16];         // 160
    float xsum[32 * 8];       // 256   [g][k]
};                            // total 27072 floats = 108288 bytes

__device__ __forceinline__ float ex2_approx(float x) {
    float y; asm("ex2.approx.ftz.f32 %0, %1;" : "=f"(y) : "f"(x)); return y;
}
__device__ __forceinline__ float rcp_approx(float x) {
    float y; asm("rcp.approx.ftz.f32 %0, %1;" : "=f"(y) : "f"(x)); return y;
}

__global__ __launch_bounds__(1024, 1)
void caps_kernel(const float* __restrict__ x_g,
                 const float* __restrict__ W,
                 const float* __restrict__ bias,
                 float* __restrict__ out) {
    extern __shared__ float smem_raw[];
    Smem* S = reinterpret_cast<Smem*>(smem_raw);

    const int b    = blockIdx.x;
    const int tid  = threadIdx.x;
    const int w    = tid >> 5;     // warp id = group g in phases A/B
    const int lane = tid & 31;

    // ---- load x for this batch (layout is already [g][k][hw] contiguous) ----
    {
        const float4* src = reinterpret_cast<const float4*>(x_g + (size_t)b * 9216);
        float4* dst = reinterpret_cast<float4*>(S->x);
        for (int i = tid; i < 9216 / 4; i += 1024) dst[i] = src[i];
    }
    __syncthreads();

    // ---- xsum[g][k] = sum_hw x (for iteration-1 uniform-c shortcut) ----
    if (tid < 256) {
        float a = 0.f;
        const float* p = S->x + tid * 36;
        #pragma unroll
        for (int t = 0; t < 36; t++) a += p[t];
        S->xsum[tid] = a;
    }
    __syncthreads();

    // iter 1: c = 1/10 uniform  ->  cx = 0.1*xsum (same for all j), csum = 3.6
    for (int i = tid; i < 2560; i += 1024) S->cx[i] = 0.1f * S->xsum[i & 255];
    if (tid < 320) S->csum[tid] = 3.6f;
    __syncthreads();

    for (int it = 0; it < 3; ++it) {
        if (it > 0) {
            // ===== Phase A: recompute b from (vW, vb, x), softmax over j -> c =====
            // warp w handles group g = w; lane -> hw, lanes 0-3 also handle hw+32
            {
                const int g = w;
                float bb[10], bb2[10];
                #pragma unroll
                for (int j = 0; j < 10; j++) {
                    float t0 = S->vb[j * 32 + g];
                    bb[j] = t0; bb2[j] = t0;
                }
                const float* xr = S->x + g * 8 * 36;
                const float* vw = S->vW;
                #pragma unroll
                for (int k = 0; k < 8; k++) {
                    float xv  = xr[k * 36 + lane];
                    float xv2 = xr[k * 36 + 32 + (lane & 3)]; // valid addr for all lanes
                    #pragma unroll
                    for (int j = 0; j < 10; j++) {
                        float wv = vw[j * 256 + g * 8 + k];   // warp-uniform broadcast
                        bb[j]  += wv * xv;
                        bb2[j] += wv * xv2;
                    }
                }
                float Z = 0.f, Z2 = 0.f;
                #pragma unroll
                for (int j = 0; j < 10; j++) {
                    bb[j]  = ex2_approx(bb[j]);   Z  += bb[j];
                    bb2[j] = ex2_approx(bb2[j]);  Z2 += bb2[j];
                }
                float r  = rcp_approx(Z);
                float r2 = rcp_approx(Z2);
                float* cw = S->c + g * 360;
                #pragma unroll
                for (int j = 0; j < 10; j++) {
                    cw[j * 36 + lane] = bb[j] * r;
                    if (lane < 4) cw[j * 36 + 32 + lane] = bb2[j] * r2;
                }
            }
            __syncthreads();

            // ===== Phase B: cx[j][g][k] = sum_hw c[j][g][hw]*x[g][k][hw]; csum =====
            // warp w = group g; lane = k*4+q; quarter q covers hw in [q*9, q*9+9)
            {
                const int g = w;
                const int k = lane >> 2, q = lane & 3;
                float acc[10], cs[10];
                #pragma unroll
                for (int j = 0; j < 10; j++) { acc[j] = 0.f; cs[j] = 0.f; }
                const float* xr = S->x + (g * 8 + k) * 36 + q * 9;
                const float* cr = S->c + g * 360 + q * 9;
                #pragma unroll
                for (int t = 0; t < 9; t++) {
                    float xv = xr[t];
                    #pragma unroll
                    for (int j = 0; j < 10; j++) {
                        float cv = cr[j * 36 + t];
                        acc[j] += cv * xv;
                        cs[j]  += cv;
                    }
                }
                #pragma unroll
                for (int j = 0; j < 10; j++) {
                    acc[j] += __shfl_xor_sync(0xffffffffu, acc[j], 1);
                    acc[j] += __shfl_xor_sync(0xffffffffu, acc[j], 2);
                    cs[j]  += __shfl_xor_sync(0xffffffffu, cs[j], 1);
                    cs[j]  += __shfl_xor_sync(0xffffffffu, cs[j], 2);
                }
                if (q == 0) {
                    #pragma unroll
                    for (int j = 0; j < 10; j++) S->cx[j * 256 + g * 8 + k] = acc[j];
                    if (k == 0) {
                        #pragma unroll
                        for (int j = 0; j < 10; j++) S->csum[j * 32 + g] = cs[j];
                    }
                }
            }
            __syncthreads();
        }

        // ===== Phase C: s[j][d] = sum_{g,k} W*cx + sum_g bias*csum =====
        // octet of 8 lanes per output pair p = j*16+d; warp handles 4 pairs
        {
            const int oct = lane >> 3, k = lane & 7;
            for (int p0 = w * 4; p0 < 160; p0 += 128) {
                const int p = p0 + oct;     // j*16+d
                const int j = p >> 4;
                float acc = 0.f;
                #pragma unroll 8
                for (int g = 0; g < 32; g++) {
                    float wv = W[g * 1280 + p * 8 + k];
                    acc += wv * S->cx[j * 256 + g * 8 + k];
                }
                if (k == 0) {
                    #pragma unroll 8
                    for (int g = 0; g < 32; g++)
                        acc += bias[g * 160 + p] * S->csum[j * 32 + g];
                }
                acc += __shfl_xor_sync(0xffffffffu, acc, 1);
                acc += __shfl_xor_sync(0xffffffffu, acc, 2);
                acc += __shfl_xor_sync(0xffffffffu, acc, 4);
                if (k == 0) S->s[p] = acc;
            }
        }
        __syncthreads();

        // ===== Phase D: squash  v = s * (||s|| / (1 + ||s||^2)) =====
        if (tid < 10) {
            const int j = tid;
            float sv[16];
            float n2 = 0.f;
            #pragma unroll
            for (int d = 0; d < 16; d++) { sv[d] = S->s[j * 16 + d]; n2 += sv[d] * sv[d]; }
            float f = sqrtf(n2) / (1.0f + n2);
            #pragma unroll
            for (int d = 0; d < 16; d++) S->v[j * 16 + d] = sv[d] * f;
        }
        __syncthreads();

        if (it == 2) {
            // final output
            if (tid < 160) out[(size_t)b * 160 + tid] = S->v[tid];
        } else {
            // ===== Phase E: accumulate vW[j][g][k] += log2e * sum_d v[j][d]*W[g,j,d,k]
            //                vb[j][g]   += log2e * sum_d v[j][d]*bias[g,j,d]
            for (int idx = tid; idx < 2560; idx += 1024) {
                const int j = idx >> 8;
                const int g = (idx >> 3) & 31, k = idx & 7;
                const float* wp = W + g * 1280 + j * 128 + k;
                float a = 0.f;
                #pragma unroll
                for (int d = 0; d < 16; d++) a += S->v[j * 16 + d] * wp[d * 8];
                if (it == 0) S->vW[idx] = LOG2E * a;
                else         S->vW[idx] += LOG2E * a;
            }
            if (tid < 320) {
                const int j = tid >> 5, g = tid & 31;
                const float* bp = bias + g * 160 + j * 16;
                float a = 0.f;
                #pragma unroll
                for (int d = 0; d < 16; d++) a += S->v[j * 16 + d] * bp[d];
                if (it == 0) S->vb[tid] = LOG2E * a;
                else         S->vb[tid] += LOG2E * a;
            }
            __syncthreads();
        }
    }
}

extern "C" void kernel_launch(void* const* d_in, const int* in_sizes, int n_in,
                              void* d_out, int out_size) {
    const float* x    = (const float*)d_in[0];
    const float* W    = (const float*)d_in[2];
    const float* bias = (const float*)d_in[3];
    float* out = (float*)d_out;

    // >48KB dynamic smem: set attribute every call (idempotent, not a stream op)
    cudaFuncSetAttribute(caps_kernel,
                         cudaFuncAttributeMaxDynamicSharedMemorySize,
                         (int)sizeof(Smem));
    caps_kernel<<<512, 1024, sizeof(Smem)>>>(x, W, bias, out);
}

// round 2
// speedup vs baseline: 1.2627x; 1.2627x over previous
#include <cuda_runtime.h>

// CapLayer fused capsule routing. 512 threads/CTA, 2 CTAs/SM.
// x:    d_in[0]  float [512][256][6][6]   (channel = g*8+k, g<32, k<8)
// targ: d_in[1]  int   (unused)
// W:    d_in[2]  float [5120][8] ; flat idx = g*1280 + j*128 + d*8 + k
// bias: d_in[3]  float [5120]    ; flat idx = g*160  + j*16  + d
// out:  float [512][10][16]

#define LOG2E 1.4426950408889634f

struct Smem {
    float x[32 * 8 * 36];     // 9216  [g][k][hw]
    float cbuf[16 * 10 * 36]; // 5760  per-warp c scratch [w][j][hw]
    float vW[10 * 32 * 8];    // 2560  [j][g][k] (accumulated, pre-scaled by log2e)
    float vb[10 * 32];        // 320   [j][g]
    float cx[10 * 32 * 8];    // 2560  [j][g][k]
    float csum[10 * 32];      // 320   [j][g]
    float sW[160];            // W-part of s
    float sB[160];            // bias-part of s
    float v[160];
    float xsum[256];          // [g][k]
};                            // 21472 floats = 85888 bytes (2 CTAs/SM: 171776 <= 227KB)

__device__ __forceinline__ float ex2_approx(float x) {
    float y; asm("ex2.approx.ftz.f32 %0, %1;" : "=f"(y) : "f"(x)); return y;
}
__device__ __forceinline__ float rcp_approx(float x) {
    float y; asm("rcp.approx.ftz.f32 %0, %1;" : "=f"(y) : "f"(x)); return y;
}

__global__ __launch_bounds__(512, 2)
void caps_kernel(const float* __restrict__ x_g,
                 const float* __restrict__ W,
                 const float* __restrict__ bias,
                 float* __restrict__ out) {
    extern __shared__ float smem_raw[];
    Smem* S = reinterpret_cast<Smem*>(smem_raw);

    const int b    = blockIdx.x;
    const int tid  = threadIdx.x;
    const int w    = tid >> 5;
    const int lane = tid & 31;

    // ---- load x (layout already [g][k][hw]) ----
    {
        const float4* src = reinterpret_cast<const float4*>(x_g + (size_t)b * 9216);
        float4* dst = reinterpret_cast<float4*>(S->x);
        #pragma unroll
        for (int i = 0; i < 5; i++) {
            int idx = tid + i * 512;
            if (idx < 2304) dst[idx] = src[idx];
        }
    }
    __syncthreads();

    // ---- xsum[g][k] = sum_hw x ----
    if (tid < 256) {
        float a = 0.f;
        const float* p = S->x + tid * 36;
        #pragma unroll
        for (int t = 0; t < 36; t++) a += p[t];
        S->xsum[tid] = a;
    }
    __syncthreads();

    // iter 1: c = 1/10 uniform -> cx = 0.1*xsum, csum = 3.6
    for (int i = tid; i < 2560; i += 512) S->cx[i] = 0.1f * S->xsum[i & 255];
    if (tid < 320) S->csum[tid] = 3.6f;
    __syncthreads();

    for (int it = 0; it < 3; ++it) {
        if (it > 0) {
            // ===== fused Phase A+B per warp; warp handles groups w and w+16 =====
            #pragma unroll
            for (int gi = 0; gi < 2; gi++) {
                const int g = w + gi * 16;
                // --- Phase A: b logits -> softmax over j -> c (per-warp buffer) ---
                {
                    float bb[10], bb2[10];
                    #pragma unroll
                    for (int j = 0; j < 10; j++) {
                        float t0 = S->vb[j * 32 + g];
                        bb[j] = t0; bb2[j] = t0;
                    }
                    const float* xr = S->x + g * 8 * 36;
                    const float* vw = S->vW;
                    #pragma unroll
                    for (int k = 0; k < 8; k++) {
                        float xv  = xr[k * 36 + lane];
                        float xv2 = xr[k * 36 + 32 + (lane & 3)];
                        #pragma unroll
                        for (int j = 0; j < 10; j++) {
                            float wv = vw[j * 256 + g * 8 + k];  // uniform broadcast
                            bb[j]  += wv * xv;
                            bb2[j] += wv * xv2;
                        }
                    }
                    float Z = 0.f, Z2 = 0.f;
                    #pragma unroll
                    for (int j = 0; j < 10; j++) {
                        bb[j]  = ex2_approx(bb[j]);   Z  += bb[j];
                        bb2[j] = ex2_approx(bb2[j]);  Z2 += bb2[j];
                    }
                    float r  = rcp_approx(Z);
                    float r2 = rcp_approx(Z2);
                    float* cw = S->cbuf + w * 360;
                    #pragma unroll
                    for (int j = 0; j < 10; j++) {
                        cw[j * 36 + lane] = bb[j] * r;
                        if (lane < 4) cw[j * 36 + 32 + lane] = bb2[j] * r2;
                    }
                }
                __syncwarp();
                // --- Phase B: cx[j][g][k] = sum_hw c*x ; csum[j][g] = sum_hw c ---
                {
                    const int k = lane >> 2, q = lane & 3;
                    float acc[10], cs[10];
                    #pragma unroll
                    for (int j = 0; j < 10; j++) { acc[j] = 0.f; cs[j] = 0.f; }
                    const float* xr = S->x + (g * 8 + k) * 36 + q * 9;
                    const float* cr = S->cbuf + w * 360 + q * 9;
                    #pragma unroll
                    for (int t = 0; t < 9; t++) {
                        float xv = xr[t];
                        #pragma unroll
                        for (int j = 0; j < 10; j++) {
                            float cv = cr[j * 36 + t];
                            acc[j] += cv * xv;
                            cs[j]  += cv;
                        }
                    }
                    #pragma unroll
                    for (int j = 0; j < 10; j++) {
                        acc[j] += __shfl_xor_sync(0xffffffffu, acc[j], 1);
                        acc[j] += __shfl_xor_sync(0xffffffffu, acc[j], 2);
                        cs[j]  += __shfl_xor_sync(0xffffffffu, cs[j], 1);
                        cs[j]  += __shfl_xor_sync(0xffffffffu, cs[j], 2);
                    }
                    if (q == 0) {
                        #pragma unroll
                        for (int j = 0; j < 10; j++) S->cx[j * 256 + g * 8 + k] = acc[j];
                        if (k == 0) {
                            #pragma unroll
                            for (int j = 0; j < 10; j++) S->csum[j * 32 + g] = cs[j];
                        }
                    }
                }
                __syncwarp();  // cbuf reuse safe for next group
            }
            __syncthreads();
        }

        // ===== Phase C: sW[p] = sum_{g,k} W*cx ; sB[p] = sum_g bias*csum =====
        {
            const int o = tid >> 3, k = lane & 7;
            // octets 0-31: pairs {o, o+64, o+128}; octets 32-63: pairs {o, o+64}
            #pragma unroll
            for (int pi = 0; pi < 3; pi++) {
                int p = o + pi * 64;
                if (pi == 2 && o >= 32) break;   // warp-uniform (octets 32+ are warps 8+)
                const int j = p >> 4;
                float acc = 0.f;
                #pragma unroll 8
                for (int g = 0; g < 32; g++)
                    acc += W[g * 1280 + p * 8 + k] * S->cx[j * 256 + g * 8 + k];
                acc += __shfl_xor_sync(0xffffffffu, acc, 1);
                acc += __shfl_xor_sync(0xffffffffu, acc, 2);
                acc += __shfl_xor_sync(0xffffffffu, acc, 4);
                if (k == 0) S->sW[p] = acc;
            }
            // bias dots on the light warps (11-15)
            if (tid >= 352) {
                const int p = tid - 352;      // 0..159
                const int j = p >> 4;
                float accb = 0.f;
                #pragma unroll 8
                for (int g = 0; g < 32; g++)
                    accb += bias[g * 160 + p] * S->csum[j * 32 + g];
                S->sB[p] = accb;
            }
        }
        __syncthreads();

        // ===== Phase D: squash (16-lane reduce), write v / out =====
        if (tid < 160) {
            const int p = tid;
            float sv = S->sW[p] + S->sB[p];
            float n2 = sv * sv;
            n2 += __shfl_xor_sync(0xffffffffu, n2, 1);
            n2 += __shfl_xor_sync(0xffffffffu, n2, 2);
            n2 += __shfl_xor_sync(0xffffffffu, n2, 4);
            n2 += __shfl_xor_sync(0xffffffffu, n2, 8);
            float f  = __fdividef(sqrtf(n2), 1.0f + n2);
            float vv = sv * f;
            S->v[p] = vv;
            if (it == 2) out[(size_t)b * 160 + p] = vv;
        }

        if (it < 2) {
            __syncthreads();
            // ===== Phase E: vW[j][g][k] += log2e*sum_d v*W ; vb likewise =====
            for (int idx = tid; idx < 2880; idx += 512) {
                if (idx < 2560) {
                    const int j = idx >> 8;
                    const int g = (idx >> 3) & 31, k = idx & 7;
                    const float* wp = W + g * 1280 + j * 128 + k;
                    float a = 0.f;
                    #pragma unroll
                    for (int d = 0; d < 16; d++) a += S->v[j * 16 + d] * wp[d * 8];
                    S->vW[idx] = (it == 0) ? LOG2E * a : S->vW[idx] + LOG2E * a;
                } else {
                    const int t2 = idx - 2560;
                    const int j = t2 >> 5, g = t2 & 31;
                    const float* bp = bias + g * 160 + j * 16;
                    float a = 0.f;
                    #pragma unroll
                    for (int d = 0; d < 16; d++) a += S->v[j * 16 + d] * bp[d];
                    S->vb[t2] = (it == 0) ? LOG2E * a : S->vb[t2] + LOG2E * a;
                }
            }
            __syncthreads();
        }
    }
}

extern "C" void kernel_launch(void* const* d_in, const int* in_sizes, int n_in,
                              void* d_out, int out_size) {
    const float* x    = (const float*)d_in[0];
    const float* W    = (const float*)d_in[2];
    const float* bias = (const float*)d_in[3];
    float* out = (float*)d_out;

    cudaFuncSetAttribute(caps_kernel,
                         cudaFuncAttributeMaxDynamicSharedMemorySize,
                         (int)sizeof(Smem));
    caps_kernel<<<512, 512, sizeof(Smem)>>>(x, W, bias, out);
}